// round 15
// baseline (speedup 1.0000x reference)
#include <cuda_runtime.h>

#define K 48
#define STOPID 47
#define CHUNK 16
#define NWARP 4
#define CLAMPV 1e32f

typedef unsigned long long ull;

// ---------- packed f32x2 helpers (Blackwell sm_103a) ----------
__device__ __forceinline__ ull pack2(float x, float y) {
    ull r;
    asm("mov.b64 %0, {%1, %2};" : "=l"(r)
        : "r"(__float_as_uint(x)), "r"(__float_as_uint(y)));
    return r;
}
__device__ __forceinline__ void unpack2(ull v, float& x, float& y) {
    unsigned int a, b;
    asm("mov.b64 {%0, %1}, %2;" : "=r"(a), "=r"(b) : "l"(v));
    x = __uint_as_float(a);
    y = __uint_as_float(b);
}
__device__ __forceinline__ ull fma2(ull a, ull b, ull c) {
    ull d;
    asm("fma.rn.f32x2 %0, %1, %2, %3;" : "=l"(d) : "l"(a), "l"(b), "l"(c));
    return d;
}
__device__ __forceinline__ ull add2(ull a, ull b) {
    ull d;
    asm("add.rn.f32x2 %0, %1, %2;" : "=l"(d) : "l"(a), "l"(b));
    return d;
}
__device__ __forceinline__ void cp_async16(unsigned int s, const void* g) {
    asm volatile("cp.async.cg.shared.global [%0], [%1], 16;" :: "r"(s), "l"(g));
}

// One warp per sequence (512 warps, 1/SMSP — proven optimal geometry).
// 48x48 matvec as 96 half-rows: lane group h in {0,1} covers j in [24h,24h+24),
// lanes l16=0..15 own rows 3*l16..3*l16+2. Per lane: 36 fma2, 6 broadcast
// LDS.128.
//
// R14 delta vs the R13 champion: the half-group combine moves OFF the serial
// chain — no shfl. Both groups atomicAdd (ATOMS.ADD.F32, no result -> no
// chain dependency) their per-half p' into ONE shared buffer; HW does the
// two-term add (order-independent -> bit-exact). 4-buffer rotation, all
// uniform (no predication): step t reads combined buf[t&3], red-adds into
// buf[(t+1)&3] (zeroed at step t-1), zeroes buf[(t+2)&3] off-chain. The
// per-step __syncwarp (retained) provides all cross-lane smem ordering.
// Carried state pr[] is per-half; masked steps re-deposit halves (sum =
// previous p, exact). Renorm divisor = combined buf[t&3][0].
//
// State in probability space: p' = exp(emit) * (E p), E = exp(trans) in 36
// packed regs. Emission exp software-pipelined one step (R13). Renorm every
// 8th step by rcp(p0_of_input), rcp/log off the chain.
__global__ __launch_bounds__(128, 1) void crf_fwd_kernel(
    const float* __restrict__ h_tag,   // [B, T, K]
    const float* __restrict__ mask,    // [B, T]
    const float* __restrict__ trans,   // [K, K]
    float* __restrict__ out,           // [B]
    int B, int T)
{
    __shared__ __align__(16) float emb[NWARP][2][CHUNK * K];  // emit chunks
    __shared__ __align__(16) float mkb[NWARP][2][CHUNK];      // mask chunks
    __shared__ __align__(16) float pb [NWARP][4][K];          // combined p, 4-rot

    const int w    = threadIdx.x >> 5;
    const int lane = threadIdx.x & 31;
    const int b    = blockIdx.x * NWARP + w;
    if (b >= B) return;

    const int l16   = lane & 15;
    const int h     = lane >> 4;
    const int row0  = 3 * l16;
    const int jbase = 24 * h;

    // E2[r][m] = ( exp(trans[row0+r][jbase+2m]), exp(trans[row0+r][jbase+2m+1]) )
    ull E2[3][12];
#pragma unroll
    for (int r = 0; r < 3; r++) {
        const float* tr = trans + (row0 + r) * K + jbase;
#pragma unroll
        for (int m = 0; m < 12; m++)
            E2[r][m] = pack2(__expf(tr[2 * m]), __expf(tr[2 * m + 1]));
    }

    const float* hb = h_tag + (size_t)b * T * K;
    const float* mb = mask + (size_t)b * T;

    // init: score = NEG except STOP=0 -> c=-1e4, p=1 normal, p_STOP clamped to
    // 1e32 (feeds only the PAD track, ~e^4000 below answer; validated R3-R13).
    // Combined buf0 = full init (both groups store identical values, WAW-safe);
    // per-half carried state: h0 = full, h1 = 0. buf1 pre-zeroed (red target
    // of step 0); bufs 2,3 are zeroed by the rotation at steps 0,1.
    float pr[3], c = -1.0e4f;
#pragma unroll
    for (int r = 0; r < 3; r++) {
        float full = (row0 + r == STOPID) ? CLAMPV : 1.0f;
        pr[r] = (h == 0) ? full : 0.0f;
        pb[w][0][row0 + r] = full;
        pb[w][1][row0 + r] = 0.0f;
    }

    const int nc    = (T + CHUNK - 1) / CHUNK;
    const int nfull = T / CHUNK;

    auto prefetch = [&](int ch) {
        const int t0n = ch * CHUNK;
        const int nb  = ch & 1;
        const size_t base = (size_t)t0n * K;
        unsigned int se = (unsigned int)__cvta_generic_to_shared(&emb[w][nb][0]);
#pragma unroll
        for (int i = 0; i < 6; i++) {     // CHUNK*K*4 = 3072B = 192 x 16B
            int seg = lane + 32 * i;
            if (base + (size_t)(seg + 1) * 4 <= (size_t)T * K)
                cp_async16(se + seg * 16, hb + base + seg * 4);
        }
        unsigned int sm = (unsigned int)__cvta_generic_to_shared(&mkb[w][nb][0]);
        if (lane < 4 && t0n + (lane + 1) * 4 <= T)
            cp_async16(sm + lane * 16, mb + t0n + lane * 4);
        asm volatile("cp.async.commit_group;");
    };

    prefetch(0);

    // ---------------- main: full 16-step chunks, 8-step unrolled bodies ----
    for (int ch = 0; ch < nfull; ch++) {
        const int cb = ch & 1;
        if (ch + 1 < nc) {
            prefetch(ch + 1);
            asm volatile("cp.async.wait_group 1;");
        } else {
            asm volatile("cp.async.wait_group 0;");
        }
        __syncwarp();   // chunk handoff: emit/mask buffers now visible

        // preload emissions/mask for step 0 of this chunk (off-chain)
        float exP0, exP1, exP2, mkP;
        {
            const float* e0 = &emb[w][cb][row0];
            exP0 = __expf(e0[0]);
            exP1 = __expf(e0[1]);
            exP2 = __expf(e0[2]);
            mkP  = mkb[w][cb][0];
        }

        for (int hf = 0; hf < 2; hf++) {
#pragma unroll
            for (int s8 = 0; s8 < 8; s8++) {
                const int  s  = hf * 8 + s8;   // hf runtime, s8 compile-time
                const int  rb = s8 & 3;        // read buf   (t&3: 16,8 ≡ 0 mod 4)
                const int  tb = (s8 + 1) & 3;  // red target (zeroed at t-1)
                const int  zb = (s8 + 2) & 3;  // zero now   (read at t+2)
                const bool RN = (s8 == 7);     // compile-time renorm predicate

                __syncwarp();

                // chain head: combined p operands (broadcast LDS.128 x6)
                const ulonglong2* pu =
                    (const ulonglong2*)(&pb[w][rb][jbase]);
                ulonglong2 u0 = pu[0], u1 = pu[1], u2 = pu[2];
                ulonglong2 u3 = pu[3], u4 = pu[4], u5 = pu[5];

                float p0in = 1.0f;
                if (RN) p0in = pb[w][rb][0];   // combined; early, off-chain

                // zero the t+2 read buffer (off-chain; dup across groups OK)
                {
                    float* pz = &pb[w][zb][row0];
                    pz[0] = 0.0f; pz[1] = 0.0f; pz[2] = 0.0f;
                }

                // prefetch NEXT step's emissions/mask ((s+1)&15 wrap; stale
                // wrapped value never consumed — chunk start re-preloads)
                const int sn = (s + 1) & 15;
                float exN0, exN1, exN2, mkN;
                {
                    const float* en = &emb[w][cb][sn * K + row0];
                    exN0 = __expf(en[0]);
                    exN1 = __expf(en[1]);
                    exN2 = __expf(en[2]);
                    mkN  = mkb[w][cb][sn];
                }

                float rv = 1.0f, lv = 0.0f;
                if (RN) {
                    asm("rcp.approx.f32 %0, %1;" : "=f"(rv) : "f"(p0in));
                    lv = __logf(p0in);
                }

                // 36 fma2, 2 accumulators per row (6-deep, 12-cyc spacing)
                ull aA[3] = {0, 0, 0};
                ull aB[3] = {0, 0, 0};
                const ulonglong2 uu[6] = {u0, u1, u2, u3, u4, u5};
#pragma unroll
                for (int i = 0; i < 6; i++) {
#pragma unroll
                    for (int r = 0; r < 3; r++) {
                        aA[r] = fma2(E2[r][2 * i],     uu[i].x, aA[r]);
                        aB[r] = fma2(E2[r][2 * i + 1], uu[i].y, aB[r]);
                    }
                }

                float sr[3];
#pragma unroll
                for (int r = 0; r < 3; r++) {
                    ull tt = add2(aA[r], aB[r]);
                    float x, y;
                    unpack2(tt, x, y);
                    sr[r] = x + y;      // this group's j-half partial
                }

                // per-half new value (no combine here — HW adds via ATOMS)
                float n0 = fminf(exP0 * sr[0], CLAMPV);
                float n1 = fminf(exP1 * sr[1], CLAMPV);
                float n2 = fminf(exP2 * sr[2], CLAMPV);

                bool upd = (mkP != 0.0f);
                pr[0] = upd ? n0 : pr[0];
                pr[1] = upd ? n1 : pr[1];
                pr[2] = upd ? n2 : pr[2];

                if (RN) {           // scale halves by rcp(p0_in): off-chain
                    pr[0] *= rv; pr[1] *= rv; pr[2] *= rv;
                    c += lv;
                }

                // deposit this group's half into the combined buffer
                atomicAdd(&pb[w][tb][row0 + 0], pr[0]);
                atomicAdd(&pb[w][tb][row0 + 1], pr[1]);
                atomicAdd(&pb[w][tb][row0 + 2], pr[2]);

                // rotate emission pipeline
                exP0 = exN0; exP1 = exN1; exP2 = exN2; mkP = mkN;
            }
        }
    }

    // ---------------- tail (T % CHUNK != 0; unused for T=1024) -------------
    int t = nfull * CHUNK;                 // t0 ≡ 0 mod 4
    if (t < T) {
        asm volatile("cp.async.wait_group 0;");
        const int cb = nfull & 1;
        for (int s = 0; t < T; s++, t++) {
            __syncwarp();
            const int rb = t & 3, tb = (t + 1) & 3, zb = (t + 2) & 3;
            const ulonglong2* pu = (const ulonglong2*)(&pb[w][rb][jbase]);
            ulonglong2 uu[6];
#pragma unroll
            for (int i = 0; i < 6; i++) uu[i] = pu[i];
            {
                float* pz = &pb[w][zb][row0];
                pz[0] = 0.0f; pz[1] = 0.0f; pz[2] = 0.0f;
            }
            const float* eb = &emb[w][cb][s * K + row0];
            float ex0 = __expf(eb[0]), ex1 = __expf(eb[1]), ex2 = __expf(eb[2]);
            float mk = mkb[w][cb][s];
            bool upd = (mk != 0.0f);
            float rv = 1.0f, lv = 0.0f;
            const bool RN = ((t & 7) == 7);
            if (RN) {
                float p0in = pb[w][rb][0];
                asm("rcp.approx.f32 %0, %1;" : "=f"(rv) : "f"(p0in));
                lv = __logf(p0in);
            }
            ull aA[3] = {0, 0, 0};
            ull aB[3] = {0, 0, 0};
#pragma unroll
            for (int i = 0; i < 6; i++) {
#pragma unroll
                for (int r = 0; r < 3; r++) {
                    aA[r] = fma2(E2[r][2 * i],     uu[i].x, aA[r]);
                    aB[r] = fma2(E2[r][2 * i + 1], uu[i].y, aB[r]);
                }
            }
            float sr[3];
#pragma unroll
            for (int r = 0; r < 3; r++) {
                ull tt = add2(aA[r], aB[r]);
                float x, y; unpack2(tt, x, y); sr[r] = x + y;
            }
            float n0 = fminf(ex0 * sr[0], CLAMPV);
            float n1 = fminf(ex1 * sr[1], CLAMPV);
            float n2 = fminf(ex2 * sr[2], CLAMPV);
            pr[0] = upd ? n0 : pr[0];
            pr[1] = upd ? n1 : pr[1];
            pr[2] = upd ? n2 : pr[2];
            if (RN) {
                pr[0] *= rv; pr[1] *= rv; pr[2] *= rv;
                c += lv;
            }
            atomicAdd(&pb[w][tb][row0 + 0], pr[0]);
            atomicAdd(&pb[w][tb][row0 + 1], pr[1]);
            atomicAdd(&pb[w][tb][row0 + 2], pr[2]);
        }
    }

    // ---------------- finalize: out = c + log( sum_k p_k e^{trans[STOP][k]} )
    // pr holds per-group HALVES: each row contributes once from each group,
    // so the full 32-lane reduction forms the combined sum automatically.
    float v;
    {
        const float* ts = trans + STOPID * K + row0;
        v = pr[0] * __expf(ts[0]) + pr[1] * __expf(ts[1]) + pr[2] * __expf(ts[2]);
    }
#pragma unroll
    for (int o = 16; o; o >>= 1)
        v += __shfl_xor_sync(0xffffffffu, v, o);
    if (lane == 0) out[b] = c + __logf(v);
}

extern "C" void kernel_launch(void* const* d_in, const int* in_sizes, int n_in,
                              void* d_out, int out_size)
{
    // Identify inputs by size: h_tag = largest, trans = smallest, mask = other
    int iH = 0, iT = 0;
    for (int i = 1; i < 3; i++) {
        if (in_sizes[i] > in_sizes[iH]) iH = i;
        if (in_sizes[i] < in_sizes[iT]) iT = i;
    }
    int iM = 3 - iH - iT;

    const float* h_tag = (const float*)d_in[iH];
    const float* mask  = (const float*)d_in[iM];
    const float* trans = (const float*)d_in[iT];
    float* out = (float*)d_out;

    int B = out_size;             // 512
    int T = in_sizes[iM] / B;     // 1024

    dim3 block(128);              // 4 warps, 1/SMSP, 1 sequence per warp
    dim3 grid((B + NWARP - 1) / NWARP);
    crf_fwd_kernel<<<grid, block>>>(h_tag, mask, trans, out, B, T);
}

// round 16
// speedup vs baseline: 2.8609x; 2.8609x over previous
#include <cuda_runtime.h>

#define K 48
#define STOPID 47
#define CHUNK 16
#define NWARP 4
#define CLAMPV 1e32f

typedef unsigned long long ull;

// ---------- packed f32x2 helpers (Blackwell sm_103a) ----------
__device__ __forceinline__ ull pack2(float x, float y) {
    ull r;
    asm("mov.b64 %0, {%1, %2};" : "=l"(r)
        : "r"(__float_as_uint(x)), "r"(__float_as_uint(y)));
    return r;
}
__device__ __forceinline__ void unpack2(ull v, float& x, float& y) {
    unsigned int a, b;
    asm("mov.b64 {%0, %1}, %2;" : "=r"(a), "=r"(b) : "l"(v));
    x = __uint_as_float(a);
    y = __uint_as_float(b);
}
__device__ __forceinline__ ull fma2(ull a, ull b, ull c) {
    ull d;
    asm("fma.rn.f32x2 %0, %1, %2, %3;" : "=l"(d) : "l"(a), "l"(b), "l"(c));
    return d;
}
__device__ __forceinline__ ull add2(ull a, ull b) {
    ull d;
    asm("add.rn.f32x2 %0, %1, %2;" : "=l"(d) : "l"(a), "l"(b));
    return d;
}
__device__ __forceinline__ void cp_async16(unsigned int s, const void* g) {
    asm volatile("cp.async.cg.shared.global [%0], [%1], 16;" :: "r"(s), "l"(g));
}

// One warp per sequence (512 warps, 1/SMSP — proven optimal geometry).
// R15: p exchange moves ENTIRELY into registers. State pr[0..2] = full p for
// rows 3*l16..3*l16+2 (identical across lane halves). Per step:
//   1) 24 shfl.idx gathers: instruction k fetches p[jbase+k] from register
//      pr[k%3] of lane 24h + k/3 (compile-time k -> uniform src reg).
//   2) pack into 12 f32x2, 36 fma2 burst (2 accs/row), tree tail.
//   3) ex-mult, shfl_xor(16) half combine, clamp, mask select vs old pr.
// NO shared memory for p: no STS, no LDS, no per-step syncwarp — shfl_sync is
// its own convergence + exchange. Emissions still via cp.async double-buffered
// 16-step chunks (off the serial chain, software-pipelined one step ahead).
// Renorm every 8th step: p0 via early shfl.idx(pr[0],0) (latency hidden under
// the burst), folded off-chain into exP and the mask fallback (R13-validated).
__global__ __launch_bounds__(128, 1) void crf_fwd_kernel(
    const float* __restrict__ h_tag,   // [B, T, K]
    const float* __restrict__ mask,    // [B, T]
    const float* __restrict__ trans,   // [K, K]
    float* __restrict__ out,           // [B]
    int B, int T)
{
    __shared__ __align__(16) float emb[NWARP][2][CHUNK * K];  // emit chunks
    __shared__ __align__(16) float mkb[NWARP][2][CHUNK];      // mask chunks

    const int w    = threadIdx.x >> 5;
    const int lane = threadIdx.x & 31;
    const int b    = blockIdx.x * NWARP + w;
    if (b >= B) return;

    const int l16     = lane & 15;
    const int h       = lane >> 4;
    const int row0    = 3 * l16;
    const int jbase   = 24 * h;
    const int srcBase = 24 * h;          // gather source lane base (own half)

    // E2[r][m] = ( exp(trans[row0+r][jbase+2m]), exp(trans[row0+r][jbase+2m+1]) )
    ull E2[3][12];
#pragma unroll
    for (int r = 0; r < 3; r++) {
        const float* tr = trans + (row0 + r) * K + jbase;
#pragma unroll
        for (int m = 0; m < 12; m++)
            E2[r][m] = pack2(__expf(tr[2 * m]), __expf(tr[2 * m + 1]));
    }

    const float* hb = h_tag + (size_t)b * T * K;
    const float* mb = mask + (size_t)b * T;

    // init: score = NEG except STOP=0 -> c=-1e4, p=1 normal, p_STOP clamped to
    // 1e32 (feeds only the PAD track, ~e^4000 below answer; validated R3-R14).
    float pr[3], c = -1.0e4f;
#pragma unroll
    for (int r = 0; r < 3; r++)
        pr[r] = (row0 + r == STOPID) ? CLAMPV : 1.0f;

    const int nc    = (T + CHUNK - 1) / CHUNK;
    const int nfull = T / CHUNK;

    auto prefetch = [&](int ch) {
        const int t0n = ch * CHUNK;
        const int nb  = ch & 1;
        const size_t base = (size_t)t0n * K;
        unsigned int se = (unsigned int)__cvta_generic_to_shared(&emb[w][nb][0]);
#pragma unroll
        for (int i = 0; i < 6; i++) {     // CHUNK*K*4 = 3072B = 192 x 16B
            int seg = lane + 32 * i;
            if (base + (size_t)(seg + 1) * 4 <= (size_t)T * K)
                cp_async16(se + seg * 16, hb + base + seg * 4);
        }
        unsigned int sm = (unsigned int)__cvta_generic_to_shared(&mkb[w][nb][0]);
        if (lane < 4 && t0n + (lane + 1) * 4 <= T)
            cp_async16(sm + lane * 16, mb + t0n + lane * 4);
        asm volatile("cp.async.commit_group;");
    };

    prefetch(0);

    // ---- one recurrence step (gather -> burst -> combine -> select) -------
    auto step = [&](int s, int sn, bool RN, const float* embc, const float* mkbc,
                    float& exP0, float& exP1, float& exP2, float& mkP) {
        // renorm broadcast issued EARLY: 26-cyc latency hides under the burst
        float p0b = 1.0f;
        if (RN) p0b = __shfl_sync(0xffffffffu, pr[0], 0);

        // 24-shfl register gather: v[k] = p[jbase + k]
        float v[24];
#pragma unroll
        for (int k = 0; k < 24; k++)
            v[k] = __shfl_sync(0xffffffffu, pr[k % 3], srcBase + k / 3);

        ull q[12];
#pragma unroll
        for (int m = 0; m < 12; m++)
            q[m] = pack2(v[2 * m], v[2 * m + 1]);

        // off-chain: next step's emissions/mask (smem, prefetched chunk)
        float exN0 = 0.f, exN1 = 0.f, exN2 = 0.f, mkN = 0.f;
        {
            const float* en = &embc[sn * K + row0];
            exN0 = __expf(en[0]);
            exN1 = __expf(en[1]);
            exN2 = __expf(en[2]);
            mkN  = mkbc[sn];
        }

        float fb0 = pr[0], fb1 = pr[1], fb2 = pr[2];   // mask fallback (full)
        if (RN) {
            float rv;
            asm("rcp.approx.f32 %0, %1;" : "=f"(rv) : "f"(p0b));
            exP0 *= rv; exP1 *= rv; exP2 *= rv;        // fold renorm off-chain
            fb0 *= rv; fb1 *= rv; fb2 *= rv;
            c += __logf(p0b);
        }

        // 36 fma2, 2 accumulators per row (6-deep chains)
        ull aA[3] = {0, 0, 0};
        ull aB[3] = {0, 0, 0};
#pragma unroll
        for (int i = 0; i < 6; i++) {
#pragma unroll
            for (int r = 0; r < 3; r++) {
                aA[r] = fma2(E2[r][2 * i],     q[2 * i],     aA[r]);
                aB[r] = fma2(E2[r][2 * i + 1], q[2 * i + 1], aB[r]);
            }
        }

        float sr[3];
#pragma unroll
        for (int r = 0; r < 3; r++) {
            ull tt = add2(aA[r], aB[r]);
            float x, y;
            unpack2(tt, x, y);
            sr[r] = x + y;                 // this half's partial
        }
        sr[0] *= exP0; sr[1] *= exP1; sr[2] *= exP2;   // ex same on partner

        // combine halves -> full p' on every lane
        sr[0] += __shfl_xor_sync(0xffffffffu, sr[0], 16);
        sr[1] += __shfl_xor_sync(0xffffffffu, sr[1], 16);
        sr[2] += __shfl_xor_sync(0xffffffffu, sr[2], 16);

        bool upd = (mkP != 0.0f);
        pr[0] = upd ? fminf(sr[0], CLAMPV) : fb0;
        pr[1] = upd ? fminf(sr[1], CLAMPV) : fb1;
        pr[2] = upd ? fminf(sr[2], CLAMPV) : fb2;

        // rotate emission pipeline
        exP0 = exN0; exP1 = exN1; exP2 = exN2; mkP = mkN;
    };

    // ---------------- main: full 16-step chunks, 8-step unrolled bodies ----
    for (int ch = 0; ch < nfull; ch++) {
        const int cb = ch & 1;
        if (ch + 1 < nc) {
            prefetch(ch + 1);
            asm volatile("cp.async.wait_group 1;");
        } else {
            asm volatile("cp.async.wait_group 0;");
        }
        __syncwarp();   // chunk handoff: emit/mask buffers now visible

        const float* embc = &emb[w][cb][0];
        const float* mkbc = &mkb[w][cb][0];

        // preload emissions/mask for step 0 of this chunk (off-chain)
        float exP0, exP1, exP2, mkP;
        {
            const float* e0 = &embc[row0];
            exP0 = __expf(e0[0]);
            exP1 = __expf(e0[1]);
            exP2 = __expf(e0[2]);
            mkP  = mkbc[0];
        }

        for (int hf = 0; hf < 2; hf++) {
#pragma unroll
            for (int s8 = 0; s8 < 8; s8++) {
                const int s = hf * 8 + s8;
                step(s, (s + 1) & 15, s8 == 7, embc, mkbc,
                     exP0, exP1, exP2, mkP);
            }
        }
    }

    // ---------------- tail (T % CHUNK != 0; unused for T=1024) -------------
    int t = nfull * CHUNK;
    if (t < T) {
        asm volatile("cp.async.wait_group 0;");
        __syncwarp();
        const int cb = nfull & 1;
        const float* embc = &emb[w][cb][0];
        const float* mkbc = &mkb[w][cb][0];
        float exP0, exP1, exP2, mkP;
        {
            const float* e0 = &embc[row0];
            exP0 = __expf(e0[0]);
            exP1 = __expf(e0[1]);
            exP2 = __expf(e0[2]);
            mkP  = mkbc[0];
        }
        for (int s = 0; t < T; s++, t++)
            step(s, (s + 1) & 15, (t & 7) == 7, embc, mkbc,
                 exP0, exP1, exP2, mkP);
    }

    // ---------------- finalize: out = c + log( sum_k p_k e^{trans[STOP][k]} )
    // pr identical on both lane halves -> only lanes 0-15 contribute.
    float v = 0.0f;
    if (lane < 16) {
        const float* ts = trans + STOPID * K + row0;
        v = pr[0] * __expf(ts[0]) + pr[1] * __expf(ts[1]) + pr[2] * __expf(ts[2]);
    }
#pragma unroll
    for (int o = 16; o; o >>= 1)
        v += __shfl_xor_sync(0xffffffffu, v, o);
    if (lane == 0) out[b] = c + __logf(v);
}

extern "C" void kernel_launch(void* const* d_in, const int* in_sizes, int n_in,
                              void* d_out, int out_size)
{
    // Identify inputs by size: h_tag = largest, trans = smallest, mask = other
    int iH = 0, iT = 0;
    for (int i = 1; i < 3; i++) {
        if (in_sizes[i] > in_sizes[iH]) iH = i;
        if (in_sizes[i] < in_sizes[iT]) iT = i;
    }
    int iM = 3 - iH - iT;

    const float* h_tag = (const float*)d_in[iH];
    const float* mask  = (const float*)d_in[iM];
    const float* trans = (const float*)d_in[iT];
    float* out = (float*)d_out;

    int B = out_size;             // 512
    int T = in_sizes[iM] / B;     // 1024

    dim3 block(128);              // 4 warps, 1/SMSP, 1 sequence per warp
    dim3 grid((B + NWARP - 1) / NWARP);
    crf_fwd_kernel<<<grid, block>>>(h_tag, mask, trans, out, B, T);
}